// round 9
// baseline (speedup 1.0000x reference)
#include <cuda_runtime.h>
#include <cstdint>

// MMDNE fused kernel, R9: R8 + software-pipelined mainloop.
// K in 8 chunks of 16, double-buffered xs via cp.async (wait_group 1):
// chunk c+1 copies overlap chunk c MMAs. XSTR=20 (bank-safe, 16B rows).
// Spans: [s 0..15][t 16..31][s_h 32..63][t_h 64..95][s_n 96..255][t_n 256..415].
// Warp w: rows 32w..32w+31 (2 m16 tiles) x 32 cols.
// Per k-step: 3 MMAs (xh*Wh, xh*Wl, xl*Wh), fp32 accum (tf32 2-term split).

#define BB   50000
#define FF   128
#define EE   32
#define NNEG 10
#define ROWS 16
#define MV   416
#define NT   416
#define XSTR 20              // xs row stride (words): bank-safe + 16B mult
#define ESTR 34
#define NCH  8               // k-chunks of 16
#define TFMASK 0xFFFFE000u

struct SmemT {
    float whi[4096];         // W hi fragments, lane-major per (kstep,ntile)
    float wlo[4096];
    float bias[EE];
    float avec[2 * EE];
    float deltas[2];
    float sq[MV];
    float dots[ROWS * 6];
    float wts[ROWS * 4];
    alignas(16) union {
        float xs[2][MV * XSTR];  // 2 x 8320 floats: double-buffered staging
        float emb[MV * ESTR];    // 14144 floats: epilogue
    } u;
};

#define MMA_TF32(d, a0, a1, a2, a3, b0, b1)                               \
    asm volatile("mma.sync.aligned.m16n8k8.row.col.f32.tf32.tf32.f32 "    \
        "{%0,%1,%2,%3}, {%4,%5,%6,%7}, {%8,%9}, {%0,%1,%2,%3};"           \
        : "+f"(d[0]), "+f"(d[1]), "+f"(d[2]), "+f"(d[3])                  \
        : "r"(a0), "r"(a1), "r"(a2), "r"(a3), "r"(b0), "r"(b1))

__device__ __forceinline__ int imin(int a, int b) { return a < b ? a : b; }

__device__ __forceinline__ void cp_async16(uint32_t smem_addr, const void* gptr) {
    asm volatile("cp.async.cg.shared.global [%0], [%1], 16;"
                 :: "r"(smem_addr), "l"(gptr) : "memory");
}
__device__ __forceinline__ void cp_commit() {
    asm volatile("cp.async.commit_group;" ::: "memory");
}

__global__ void __launch_bounds__(NT, 2) mmdne_kernel(
    const float* __restrict__ s_fts, const float* __restrict__ t_fts,
    const float* __restrict__ s_h_fts, const float* __restrict__ t_h_fts,
    const float* __restrict__ s_neg_fts, const float* __restrict__ t_neg_fts,
    const float* __restrict__ event_time,
    const float* __restrict__ s_h_times, const float* __restrict__ t_h_times,
    const float* __restrict__ s_h_mask, const float* __restrict__ t_h_mask,
    const float* __restrict__ W_fts, const float* __restrict__ b_fts,
    const float* __restrict__ a_vec,
    const float* __restrict__ delta_s, const float* __restrict__ delta_t,
    float* __restrict__ out)
{
    extern __shared__ char smem_raw[];
    SmemT& sm = *reinterpret_cast<SmemT*>(smem_raw);
    const int tid  = threadIdx.x;
    const int wid  = tid >> 5;
    const int lane = tid & 31;
    const int g    = lane >> 2;
    const int tg   = lane & 3;
    const int row_base = blockIdx.x * ROWS;

    // ---- Phase 0: params + W -> hi/lo tf32-split fragments ----
    if (tid < EE)     sm.bias[tid] = b_fts[tid];
    if (tid < 2 * EE) sm.avec[tid] = a_vec[tid];
    if (tid == 0) { sm.deltas[0] = delta_s[0]; sm.deltas[1] = delta_t[0]; }
    for (int idx = tid; idx < 4096; idx += NT) {
        int s   = idx >> 8;             // kstep 0..15
        int rem = idx & 255;
        int ntl = rem >> 6;             // ntile 0..3
        int l   = (rem >> 1) & 31;      // lane
        int wh  = idx & 1;
        int gg  = l >> 2, tt = l & 3;
        int k   = 8 * s + tt + (wh ? 4 : 0);
        int e   = 8 * ntl + gg;
        float w = W_fts[k * EE + e];
        uint32_t hb = __float_as_uint(w) & TFMASK;
        sm.whi[idx] = __uint_as_float(hb);
        sm.wlo[idx] = w - __uint_as_float(hb);
    }

    // ---- hoisted per-thread staging descriptor (4 float4 per chunk) ----
    const float* gptr[4];
    uint32_t sts_off[4];
    {
        const uint32_t xs0 = (uint32_t)__cvta_generic_to_shared(sm.u.xs[0]);
#pragma unroll
        for (int i = 0; i < 4; ++i) {
            int idx = tid + i * NT;        // 0..1663
            int m = idx >> 2;              // vector-row 0..415
            int q = idx & 3;               // float4 index within 16-k chunk
            const float* gp;
            if (m < 16)       gp = s_fts     + (long)imin(row_base + m,            BB - 1)      * FF;
            else if (m < 32)  gp = t_fts     + (long)imin(row_base + m - 16,       BB - 1)      * FF;
            else if (m < 64)  gp = s_h_fts   + (long)imin(row_base * 2 + m - 32,   2 * BB - 1)  * FF;
            else if (m < 96)  gp = t_h_fts   + (long)imin(row_base * 2 + m - 64,   2 * BB - 1)  * FF;
            else if (m < 256) gp = s_neg_fts + (long)imin(row_base * 10 + m - 96,  10 * BB - 1) * FF;
            else              gp = t_neg_fts + (long)imin(row_base * 10 + m - 256, 10 * BB - 1) * FF;
            gptr[i] = gp + 4 * q;
            sts_off[i] = xs0 + (uint32_t)((m * XSTR + 4 * q) * 4);
        }
    }
    const uint32_t buf_stride = (uint32_t)(MV * XSTR * 4);

    float acc[2][4][4];
#pragma unroll
    for (int mt = 0; mt < 2; ++mt)
#pragma unroll
        for (int nt = 0; nt < 4; ++nt)
#pragma unroll
            for (int j = 0; j < 4; ++j) acc[mt][nt][j] = 0.f;

    // ---- prologue: issue chunk 0 ----
#pragma unroll
    for (int i = 0; i < 4; ++i) cp_async16(sts_off[i], gptr[i]);
    cp_commit();

    // ---- pipelined mainloop over 8 chunks of 16 k ----
#pragma unroll 1
    for (int c = 0; c < NCH; ++c) {
        if (c + 1 < NCH) {
            const uint32_t dst = ((c + 1) & 1) ? buf_stride : 0u;
            const float* gofs = (const float*)0 + 16 * (c + 1);
            (void)gofs;
#pragma unroll
            for (int i = 0; i < 4; ++i)
                cp_async16(sts_off[i] + dst, gptr[i] + 16 * (c + 1));
            cp_commit();
            asm volatile("cp.async.wait_group 1;" ::: "memory");
        } else {
            asm volatile("cp.async.wait_group 0;" ::: "memory");
        }
        __syncthreads();   // chunk c data visible to all warps

        const float* xw = sm.u.xs[c & 1] + (wid * 32) * XSTR;
#pragma unroll
        for (int kt = 0; kt < 2; ++kt) {
            const int sg = c * 2 + kt;
            uint32_t bh[4][2], bl[4][2];
#pragma unroll
            for (int nt = 0; nt < 4; ++nt) {
                float2 h  = *reinterpret_cast<const float2*>(&sm.whi[(sg * 4 + nt) * 64 + lane * 2]);
                float2 lo = *reinterpret_cast<const float2*>(&sm.wlo[(sg * 4 + nt) * 64 + lane * 2]);
                bh[nt][0] = __float_as_uint(h.x);  bh[nt][1] = __float_as_uint(h.y);
                bl[nt][0] = __float_as_uint(lo.x); bl[nt][1] = __float_as_uint(lo.y);
            }
#pragma unroll
            for (int mt = 0; mt < 2; ++mt) {
                const float* ap = xw + (16 * mt + g) * XSTR + 8 * kt + tg;
                float a0f = ap[0];
                float a1f = ap[8 * XSTR];
                float a2f = ap[4];
                float a3f = ap[8 * XSTR + 4];
                uint32_t ah0 = __float_as_uint(a0f) & TFMASK;
                uint32_t ah1 = __float_as_uint(a1f) & TFMASK;
                uint32_t ah2 = __float_as_uint(a2f) & TFMASK;
                uint32_t ah3 = __float_as_uint(a3f) & TFMASK;
                uint32_t al0 = __float_as_uint(a0f - __uint_as_float(ah0));
                uint32_t al1 = __float_as_uint(a1f - __uint_as_float(ah1));
                uint32_t al2 = __float_as_uint(a2f - __uint_as_float(ah2));
                uint32_t al3 = __float_as_uint(a3f - __uint_as_float(ah3));
#pragma unroll
                for (int nt = 0; nt < 4; ++nt) {
                    MMA_TF32(acc[mt][nt], ah0, ah1, ah2, ah3, bh[nt][0], bh[nt][1]);
                    MMA_TF32(acc[mt][nt], ah0, ah1, ah2, ah3, bl[nt][0], bl[nt][1]);
                    MMA_TF32(acc[mt][nt], al0, al1, al2, al3, bh[nt][0], bh[nt][1]);
                }
            }
        }
        __syncthreads();   // MMA(c) done before iter c+1 issues into buf[c&1]
    }

    // ---- Epilogue A: bias add, emb stores, sqnorms, a-projections ----
#pragma unroll
    for (int mt = 0; mt < 2; ++mt) {
        const int r1 = wid * 32 + mt * 16 + g;
        const int r2 = r1 + 8;
        const float* av1 = sm.avec + ((r1 < 32) ? 0 : EE);
        const float* av2 = sm.avec + ((r2 < 32) ? 0 : EE);
        float s1 = 0.f, s2 = 0.f, d1 = 0.f, d2 = 0.f;
#pragma unroll
        for (int nt = 0; nt < 4; ++nt) {
            const int col = nt * 8 + tg * 2;
            float b0 = sm.bias[col], b1v = sm.bias[col + 1];
            float e0 = acc[mt][nt][0] + b0, e1 = acc[mt][nt][1] + b1v;
            float e2 = acc[mt][nt][2] + b0, e3 = acc[mt][nt][3] + b1v;
            *reinterpret_cast<float2*>(&sm.u.emb[r1 * ESTR + col]) = make_float2(e0, e1);
            *reinterpret_cast<float2*>(&sm.u.emb[r2 * ESTR + col]) = make_float2(e2, e3);
            s1 += e0 * e0 + e1 * e1;
            s2 += e2 * e2 + e3 * e3;
            d1 += e0 * av1[col] + e1 * av1[col + 1];
            d2 += e2 * av2[col] + e3 * av2[col + 1];
        }
        s1 += __shfl_xor_sync(0xFFFFFFFFu, s1, 1); s1 += __shfl_xor_sync(0xFFFFFFFFu, s1, 2);
        s2 += __shfl_xor_sync(0xFFFFFFFFu, s2, 1); s2 += __shfl_xor_sync(0xFFFFFFFFu, s2, 2);
        d1 += __shfl_xor_sync(0xFFFFFFFFu, d1, 1); d1 += __shfl_xor_sync(0xFFFFFFFFu, d1, 2);
        d2 += __shfl_xor_sync(0xFFFFFFFFu, d2, 1); d2 += __shfl_xor_sync(0xFFFFFFFFu, d2, 2);
        if (tg == 0) {
            sm.sq[r1] = s1;
            sm.sq[r2] = s2;
            // dots slots: s->0, t->1, s_h->2+h, t_h->4+h
            int mm = r1; float dd = d1;
#pragma unroll
            for (int rep = 0; rep < 2; ++rep) {
                if (mm < 16)      sm.dots[mm * 6 + 0] = dd;
                else if (mm < 32) sm.dots[(mm - 16) * 6 + 1] = dd;
                else if (mm < 64) sm.dots[((mm - 32) >> 1) * 6 + 2 + ((mm - 32) & 1)] = dd;
                else if (mm < 96) sm.dots[((mm - 64) >> 1) * 6 + 4 + ((mm - 64) & 1)] = dd;
                mm = r2; dd = d2;
            }
        }
    }
    __syncthreads();

    // ---- Epilogue B: per-row attention weights (16 threads) ----
    if (tid < ROWS) {
        const int r = tid;
        int rg = row_base + r; if (rg >= BB) rg = BB - 1;
        const float ds = sm.deltas[0];
        const float dt = sm.deltas[1];
        const float et = event_time[rg];

        float dts0 = fabsf(et - s_h_times[rg * 2 + 0]);
        float dts1 = fabsf(et - s_h_times[rg * 2 + 1]);
        float sc0 = sm.dots[r * 6 + 0] + sm.dots[r * 6 + 2];
        float sc1 = sm.dots[r * 6 + 0] + sm.dots[r * 6 + 3];
        float sim0 = expf(-ds * dts0) * sc0; sim0 = (sim0 > 0.f) ? sim0 : 0.2f * sim0;
        float sim1 = expf(-ds * dts1) * sc1; sim1 = (sim1 > 0.f) ? sim1 : 0.2f * sim1;
        float mx = fmaxf(sim0, sim1);
        float e0 = expf(sim0 - mx), e1 = expf(sim1 - mx);
        float inv = 1.f / (e0 + e1);
        sm.wts[r * 4 + 0] = e0 * inv * expf(ds * dts0) * s_h_mask[rg * 2 + 0];
        sm.wts[r * 4 + 1] = e1 * inv * expf(ds * dts1) * s_h_mask[rg * 2 + 1];

        float dtt0 = fabsf(et - t_h_times[rg * 2 + 0]);
        float dtt1 = fabsf(et - t_h_times[rg * 2 + 1]);
        float tc0 = sm.dots[r * 6 + 1] + sm.dots[r * 6 + 4];
        float tc1 = sm.dots[r * 6 + 1] + sm.dots[r * 6 + 5];
        float tm0 = expf(-dt * dtt0) * tc0; tm0 = (tm0 > 0.f) ? tm0 : 0.2f * tm0;
        float tm1 = expf(-dt * dtt1) * tc1; tm1 = (tm1 > 0.f) ? tm1 : 0.2f * tm1;
        float mx2 = fmaxf(tm0, tm1);
        float f0 = expf(tm0 - mx2), f1 = expf(tm1 - mx2);
        float inv2 = 1.f / (f0 + f1);
        sm.wts[r * 4 + 2] = f0 * inv2 * expf(dt * dtt0) * t_h_mask[rg * 2 + 0];
        sm.wts[r * 4 + 3] = f1 * inv2 * expf(dt * dtt1) * t_h_mask[rg * 2 + 1];
    }
    __syncthreads();

    // ---- Epilogue C: 21 outputs per row ----
    // Row map: s=r, t=16+r, s_h=32+2r+h, t_h=64+2r+h, s_n=96+10r+n, t_n=256+10r+n
    for (int it = tid; it < ROWS * 21; it += NT) {
        const int r = it / 21;
        const int k = it % 21;
        const int rg = row_base + r;
        if (rg >= BB) continue;
        const float* E = sm.u.emb;

        if (k == 0) {
            const float* es  = E + (r) * ESTR;
            const float* etb = E + (16 + r) * ESTR;
            const float* h0  = E + (32 + 2 * r) * ESTR;
            const float* h1  = E + (33 + 2 * r) * ESTR;
            float pm = 0.f, pa0 = 0.f, pa1 = 0.f;
#pragma unroll
            for (int e = 0; e < EE; ++e) {
                float te = etb[e];
                float d0 = es[e] - te; pm  -= d0 * d0;
                float d1 = h0[e] - te; pa0 -= d1 * d1;
                float d2 = h1[e] - te; pa1 -= d2 * d2;
            }
            out[rg] = pm + sm.wts[r * 4 + 0] * pa0 + sm.wts[r * 4 + 1] * pa1;
        } else if (k <= 10) {
            const int n = k - 1;
            const float* en = E + (256 + 10 * r + n) * ESTR;   // t_neg
            const float* es = E + (r) * ESTR;
            const float* h0 = E + (32 + 2 * r) * ESTR;
            const float* h1 = E + (33 + 2 * r) * ESTR;
            float d_s = 0.f, d0 = 0.f, d1 = 0.f;
#pragma unroll
            for (int e = 0; e < EE; ++e) {
                float x = en[e];
                d_s += es[e] * x;
                d0  += h0[e] * x;
                d1  += h1[e] * x;
            }
            float sqn = sm.sq[256 + 10 * r + n];
            float nmu = -(sm.sq[r] + sqn - 2.f * d_s);
            float na0 = -(sm.sq[32 + 2 * r] + sqn - 2.f * d0);
            float na1 = -(sm.sq[33 + 2 * r] + sqn - 2.f * d1);
            out[BB + (long)rg * NNEG + n] =
                nmu + sm.wts[r * 4 + 0] * na0 + sm.wts[r * 4 + 1] * na1;
        } else {
            const int n = k - 11;
            const float* en  = E + (96 + 10 * r + n) * ESTR;   // s_neg
            const float* et2 = E + (16 + r) * ESTR;
            const float* h0  = E + (64 + 2 * r) * ESTR;
            const float* h1  = E + (65 + 2 * r) * ESTR;
            float d_t = 0.f, d0 = 0.f, d1 = 0.f;
#pragma unroll
            for (int e = 0; e < EE; ++e) {
                float x = en[e];
                d_t += et2[e] * x;
                d0  += h0[e] * x;
                d1  += h1[e] * x;
            }
            float sqn = sm.sq[96 + 10 * r + n];
            float nmu = -(sm.sq[16 + r] + sqn - 2.f * d_t);
            float na0 = -(sm.sq[64 + 2 * r] + sqn - 2.f * d0);
            float na1 = -(sm.sq[65 + 2 * r] + sqn - 2.f * d1);
            out[BB + (long)BB * NNEG + (long)rg * NNEG + n] =
                nmu + sm.wts[r * 4 + 2] * na0 + sm.wts[r * 4 + 3] * na1;
        }
    }
}

extern "C" void kernel_launch(void* const* d_in, const int* in_sizes, int n_in,
                              void* d_out, int out_size)
{
    const float* s_fts      = (const float*)d_in[0];
    const float* t_fts      = (const float*)d_in[1];
    const float* s_h_fts    = (const float*)d_in[2];
    const float* t_h_fts    = (const float*)d_in[3];
    const float* s_neg_fts  = (const float*)d_in[4];
    const float* t_neg_fts  = (const float*)d_in[5];
    const float* event_time = (const float*)d_in[6];
    const float* s_h_times  = (const float*)d_in[7];
    const float* t_h_times  = (const float*)d_in[8];
    const float* s_h_mask   = (const float*)d_in[9];
    const float* t_h_mask   = (const float*)d_in[10];
    const float* W_fts      = (const float*)d_in[11];
    const float* b_fts      = (const float*)d_in[12];
    const float* a_vec      = (const float*)d_in[13];
    const float* delta_s    = (const float*)d_in[14];
    const float* delta_t    = (const float*)d_in[15];
    float* out = (float*)d_out;

    const int smem_bytes = (int)sizeof(SmemT);
    cudaFuncSetAttribute(mmdne_kernel,
                         cudaFuncAttributeMaxDynamicSharedMemorySize, smem_bytes);

    const int nblocks = BB / ROWS;   // 3125 exact
    mmdne_kernel<<<nblocks, NT, smem_bytes>>>(
        s_fts, t_fts, s_h_fts, t_h_fts, s_neg_fts, t_neg_fts,
        event_time, s_h_times, t_h_times, s_h_mask, t_h_mask,
        W_fts, b_fts, a_vec, delta_s, delta_t, out);
}